// round 14
// baseline (speedup 1.0000x reference)
#include <cuda_runtime.h>
#include <cstdint>

#define FM      14
#define HW      196          // 14*14
#define CH      2048
#define CHUNKS  16
#define CPC     (CH / CHUNKS)   // 128 channels per chunk
#define NWIN    361
#define MAXB    64

// Per-batch channel sums, accumulated via RED.ADD.F32 by the 16 chunk blocks.
// Zero at load; reset to zero by the finalize kernel each run.
__device__ float g_sum[MAXB * HW];
// Per-batch arrival counters. Zero at load; reset by finalize each run.
__device__ int g_count[MAXB];

__device__ __forceinline__ int atom_add_release_gpu(int* p, int v) {
    int old;
    asm volatile("atom.add.release.gpu.global.s32 %0, [%1], %2;"
                 : "=r"(old) : "l"(p), "r"(v) : "memory");
    return old;
}
__device__ __forceinline__ int ld_acquire_gpu(const int* p) {
    int v;
    asm volatile("ld.acquire.gpu.global.s32 %0, [%1];" : "=r"(v) : "l"(p) : "memory");
    return v;
}
__device__ __forceinline__ float ld_acquire_f32(const float* p) {
    float v;
    asm volatile("ld.acquire.gpu.global.f32 %0, [%1];" : "=f"(v) : "l"(p) : "memory");
    return v;
}
__device__ __forceinline__ void red_add_f32(float* p, float v) {
    asm volatile("red.global.add.f32 [%0], %1;" :: "l"(p), "f"(v) : "memory");
}

// Monotonic float<->uint bijection (total order preserved).
__device__ __forceinline__ uint32_t f2key(float f) {
    uint32_t u = __float_as_uint(f);
    return (u & 0x80000000u) ? ~u : (u | 0x80000000u);
}
__device__ __forceinline__ float key2f(uint32_t k) {
    uint32_t u = (k & 0x80000000u) ? (k ^ 0x80000000u) : ~k;
    return __uint_as_float(u);
}

// ---------------------------------------------------------------------------
// Kernel 1: lean streaming reduction (exact R12 form): LDG.128 unroll 8,
// PDL trigger, RED.ADD accumulation into g_sum, release-atomic arrival.
// ---------------------------------------------------------------------------
__global__ __launch_bounds__(196) void chan_sum_kernel(const float* __restrict__ x, int B) {
    asm volatile("griddepcontrol.launch_dependents;" ::: "memory");

    const int b     = blockIdx.x;
    const int chunk = blockIdx.y;
    const int tid   = threadIdx.x;          // 0..195
    const int grp   = tid / 49;             // 0..3
    const int v     = tid - grp * 49;       // 0..48

    const float4* base = reinterpret_cast<const float4*>(
        x + ((size_t)b * CH + (size_t)chunk * CPC) * HW);

    float4 acc = make_float4(0.f, 0.f, 0.f, 0.f);
#pragma unroll 8
    for (int c = grp; c < CPC; c += 4) {
        float4 t = base[c * 49 + v];
        acc.x += t.x; acc.y += t.y; acc.z += t.z; acc.w += t.w;
    }

    __shared__ float4 red[4 * 49];
    red[grp * 49 + v] = acc;
    __syncthreads();

    if (tid < HW) {
        const float* rf = reinterpret_cast<const float*>(red);
        red_add_f32(&g_sum[b * HW + tid],
                    rf[tid] + rf[HW + tid] + rf[2 * HW + tid] + rf[3 * HW + tid]);
    }
    __syncthreads();
    if (tid == 0) (void)atom_add_release_gpu(&g_count[b], 1);
}

// ---------------------------------------------------------------------------
// Kernel 2: finalize (PDL co-scheduled), latency-optimized tail.
//  - per-warp lane0 tight poll on the batch's arrival counter
//  - single __syncthreads on the critical path (after ssum fill)
//  - warps 0..2: per-group NMS entirely in registers; argmax via
//    __reduce_max_sync on a sortable key + __reduce_min_sync index tie-break;
//    best box decoded arithmetically from the window index (no cbox, no shfl)
//  - warps 3..11: compute + write all 361 window scores to gmem in parallel
// Output layout (fp32): [B*7 indices][B*7 window scores][B*361 all_scores]
// ---------------------------------------------------------------------------
__global__ __launch_bounds__(384) void appm_finalize_kernel(float* __restrict__ out, int B)
{
    const int b    = blockIdx.x;
    const int tid  = threadIdx.x;
    const int wid  = tid >> 5;
    const int lane = tid & 31;

    __shared__ float ssum[HW];

    // Wait for this batch's 16 chunk partials (per-warp lane0 tight poll).
    if (lane == 0) {
        while (ld_acquire_gpu(&g_count[b]) < CHUNKS) {}
    }
    __syncwarp();

    if (tid < HW) {
        ssum[tid] = ld_acquire_f32(&g_sum[b * HW + tid]);
        g_sum[b * HW + tid] = 0.f;   // reset for next graph replay
    }
    __syncthreads();
    if (tid == 0) g_count[b] = 0;    // all warps are past the poll now

    if (wid < 3) {
        // ---- NMS, one warp per ratio group --------------------------------
        const int starts[3] = {0, 121, 241};
        const int counts[3] = {121, 120, 120};
        const int ns[3]     = {2, 3, 2};
        const int outoff[3] = {0, 2, 5};
        const int rhs[3]    = {4, 3, 5};
        const int rws[3]    = {4, 5, 3};
        const int Ws[3]     = {11, 10, 12};

        const int st  = starts[wid];
        const int cnt = counts[wid];
        const int n   = ns[wid];
        const int rh  = rhs[wid];
        const int rw  = rws[wid];
        const int W   = Ws[wid];
        const float A = (float)(rh * 32 * rw * 32);   // constant box area

        float sc[4];
        float bx0[4], by0[4], bx1[4], by1[4];
        bool  alive[4];
#pragma unroll
        for (int k = 0; k < 4; k++) {
            int ii = k * 32 + lane;
            bool valid = (ii < cnt);
            alive[k] = valid;
            int ci = valid ? (ii / W) : 0;
            int cj = valid ? (ii % W) : 0;
            // window score (identical FP op order to the all_scores path)
            float s = 0.f;
            for (int di = 0; di < rh; di++)
                for (int dj = 0; dj < rw; dj++)
                    s += ssum[(ci + di) * FM + (cj + dj)];
            sc[k] = s / (float)(rh * rw);
            bx0[k] = (float)(cj * 32);
            by0[k] = (float)(ci * 32);
            bx1[k] = (float)((cj + rw) * 32);
            by1[k] = (float)((ci + rh) * 32);
        }

        for (int step = 0; step < n; step++) {
            // per-lane best (smallest k first => smallest index among lane's ties)
            uint32_t bkey = 0u;
            int      bidx = 0x7FFFFFFF;
#pragma unroll
            for (int k = 0; k < 4; k++) {
                if (alive[k]) {
                    uint32_t key = f2key(sc[k]);
                    if (key > bkey) { bkey = key; bidx = k * 32 + lane; }
                }
            }
            uint32_t wmax = __reduce_max_sync(0xFFFFFFFFu, bkey);
            int cand = (bkey == wmax) ? bidx : 0x7FFFFFFF;
            int bi   = __reduce_min_sync(0xFFFFFFFFu, cand);
            float bsc = key2f(wmax);

            if (lane == 0) {
                out[b * 7 + outoff[wid] + step]         = (float)(st + bi);
                out[7 * B + b * 7 + outoff[wid] + step] = bsc;
            }

            // best box from index (pure ALU, no shuffles)
            int   Bi = bi / W, Bj = bi % W;
            float BX0 = (float)(Bj * 32);
            float BY0 = (float)(Bi * 32);
            float BX1 = (float)((Bj + rw) * 32);
            float BY1 = (float)((Bi + rh) * 32);

#pragma unroll
            for (int k = 0; k < 4; k++) {
                float ix0 = fmaxf(BX0, bx0[k]);
                float iy0 = fmaxf(BY0, by0[k]);
                float ix1 = fminf(BX1, bx1[k]);
                float iy1 = fminf(BY1, by1[k]);
                float inter = fmaxf(ix1 - ix0, 0.f) * fmaxf(iy1 - iy0, 0.f);
                float iou = inter / (A + A - inter);
                if (!(iou < 0.25f)) alive[k] = false;
            }
        }
    } else {
        // ---- warps 3..11: all 361 window scores to gmem -------------------
        float* all_scores_out = out + 14 * B;
        for (int w = tid - 96; w < NWIN; w += 288) {
            int i, j, rh, rw;
            if (w < 121)      { rh = 4; rw = 4; int l = w;       i = l / 11; j = l % 11; }
            else if (w < 241) { rh = 3; rw = 5; int l = w - 121; i = l / 10; j = l % 10; }
            else              { rh = 5; rw = 3; int l = w - 241; i = l / 12; j = l % 12; }
            float s = 0.f;
            for (int di = 0; di < rh; di++)
                for (int dj = 0; dj < rw; dj++)
                    s += ssum[(i + di) * FM + (j + dj)];
            all_scores_out[b * NWIN + w] = s / (float)(rh * rw);
        }
    }
}

extern "C" void kernel_launch(void* const* d_in, const int* in_sizes, int n_in,
                              void* d_out, int out_size) {
    const float* x   = (const float*)d_in[0];
    float*       out = (float*)d_out;

    const int B = in_sizes[0] / (CH * HW);   // 64

    dim3 grid1(B, CHUNKS);
    chan_sum_kernel<<<grid1, 196>>>(x, B);

    cudaLaunchConfig_t cfg = {};
    cfg.gridDim  = dim3(B, 1, 1);
    cfg.blockDim = dim3(384, 1, 1);
    cfg.dynamicSmemBytes = 0;
    cfg.stream = 0;
    cudaLaunchAttribute attrs[1];
    attrs[0].id = cudaLaunchAttributeProgrammaticStreamSerialization;
    attrs[0].val.programmaticStreamSerializationAllowed = 1;
    cfg.attrs = attrs;
    cfg.numAttrs = 1;

    cudaError_t err = cudaLaunchKernelEx(&cfg, appm_finalize_kernel, out, B);
    if (err != cudaSuccess) {
        (void)cudaGetLastError();   // clear
        appm_finalize_kernel<<<B, 384>>>(out, B);
    }
}

// round 15
// speedup vs baseline: 1.0185x; 1.0185x over previous
#include <cuda_runtime.h>
#include <cstdint>

#define FM      14
#define HW      196          // 14*14
#define CH      2048
#define CHUNKS  16
#define CPC     (CH / CHUNKS)   // 128 channels per chunk
#define NWIN    361
#define MAXB    64

// Per-batch channel sums, accumulated via RED.ADD.F32 by the 16 chunk blocks.
// Zero at load; reset to zero by the finalize kernel each run.
__device__ float g_sum[MAXB * HW];
// Per-batch arrival counters. Zero at load; reset by finalize each run.
__device__ int g_count[MAXB];

__device__ __forceinline__ int atom_add_release_gpu(int* p, int v) {
    int old;
    asm volatile("atom.add.release.gpu.global.s32 %0, [%1], %2;"
                 : "=r"(old) : "l"(p), "r"(v) : "memory");
    return old;
}
__device__ __forceinline__ int ld_acquire_gpu(const int* p) {
    int v;
    asm volatile("ld.acquire.gpu.global.s32 %0, [%1];" : "=r"(v) : "l"(p) : "memory");
    return v;
}
__device__ __forceinline__ void red_add_f32(float* p, float v) {
    asm volatile("red.global.add.f32 [%0], %1;" :: "l"(p), "f"(v) : "memory");
}

// Monotonic float<->uint bijection (total order preserved).
__device__ __forceinline__ uint32_t f2key(float f) {
    uint32_t u = __float_as_uint(f);
    return (u & 0x80000000u) ? ~u : (u | 0x80000000u);
}
__device__ __forceinline__ float key2f(uint32_t k) {
    uint32_t u = (k & 0x80000000u) ? (k ^ 0x80000000u) : ~k;
    return __uint_as_float(u);
}

// ---------------------------------------------------------------------------
// Kernel 1: lean streaming reduction (exact R12 form): LDG.128 unroll 8,
// PDL trigger, RED.ADD accumulation into g_sum, release-atomic arrival.
// ---------------------------------------------------------------------------
__global__ __launch_bounds__(196) void chan_sum_kernel(const float* __restrict__ x, int B) {
    asm volatile("griddepcontrol.launch_dependents;" ::: "memory");

    const int b     = blockIdx.x;
    const int chunk = blockIdx.y;
    const int tid   = threadIdx.x;          // 0..195
    const int grp   = tid / 49;             // 0..3
    const int v     = tid - grp * 49;       // 0..48

    const float4* base = reinterpret_cast<const float4*>(
        x + ((size_t)b * CH + (size_t)chunk * CPC) * HW);

    float4 acc = make_float4(0.f, 0.f, 0.f, 0.f);
#pragma unroll 8
    for (int c = grp; c < CPC; c += 4) {
        float4 t = base[c * 49 + v];
        acc.x += t.x; acc.y += t.y; acc.z += t.z; acc.w += t.w;
    }

    __shared__ float4 red[4 * 49];
    red[grp * 49 + v] = acc;
    __syncthreads();

    if (tid < HW) {
        const float* rf = reinterpret_cast<const float*>(red);
        red_add_f32(&g_sum[b * HW + tid],
                    rf[tid] + rf[HW + tid] + rf[2 * HW + tid] + rf[3 * HW + tid]);
    }
    __syncthreads();
    if (tid == 0) (void)atom_add_release_gpu(&g_count[b], 1);
}

// ---------------------------------------------------------------------------
// Kernel 2: finalize (PDL co-scheduled).
//  WAIT: exactly the proven R12 form — single tid==0 poller with nanosleep
//        (no chip-wide polling pressure on L2 while kernel 1 streams).
//  TAIL: R13's lean form — register NMS with HW redux argmax, arithmetic
//        box decode, all_scores written by warps 3..11 in parallel.
// Output layout (fp32): [B*7 indices][B*7 window scores][B*361 all_scores]
// ---------------------------------------------------------------------------
__global__ __launch_bounds__(384) void appm_finalize_kernel(float* __restrict__ out, int B)
{
    const int b    = blockIdx.x;
    const int tid  = threadIdx.x;
    const int wid  = tid >> 5;
    const int lane = tid & 31;

    __shared__ float ssum[HW];

    // Wait for this batch's 16 chunk partials (single low-pressure poller).
    if (tid == 0) {
        while (ld_acquire_gpu(&g_count[b]) < CHUNKS) __nanosleep(32);
        g_count[b] = 0;   // reset for next graph replay
    }
    __syncthreads();

    if (tid < HW) {
        ssum[tid] = __ldcg(&g_sum[b * HW + tid]);
        g_sum[b * HW + tid] = 0.f;   // reset for next graph replay
    }
    __syncthreads();

    if (wid < 3) {
        // ---- NMS, one warp per ratio group --------------------------------
        const int starts[3] = {0, 121, 241};
        const int counts[3] = {121, 120, 120};
        const int ns[3]     = {2, 3, 2};
        const int outoff[3] = {0, 2, 5};
        const int rhs[3]    = {4, 3, 5};
        const int rws[3]    = {4, 5, 3};
        const int Ws[3]     = {11, 10, 12};

        const int st  = starts[wid];
        const int cnt = counts[wid];
        const int n   = ns[wid];
        const int rh  = rhs[wid];
        const int rw  = rws[wid];
        const int W   = Ws[wid];
        const float A = (float)(rh * 32 * rw * 32);   // constant box area

        float sc[4];
        float bx0[4], by0[4], bx1[4], by1[4];
        bool  alive[4];
#pragma unroll
        for (int k = 0; k < 4; k++) {
            int ii = k * 32 + lane;
            bool valid = (ii < cnt);
            alive[k] = valid;
            int ci = valid ? (ii / W) : 0;
            int cj = valid ? (ii % W) : 0;
            // window score (identical FP op order to the all_scores path)
            float s = 0.f;
            for (int di = 0; di < rh; di++)
                for (int dj = 0; dj < rw; dj++)
                    s += ssum[(ci + di) * FM + (cj + dj)];
            sc[k] = s / (float)(rh * rw);
            bx0[k] = (float)(cj * 32);
            by0[k] = (float)(ci * 32);
            bx1[k] = (float)((cj + rw) * 32);
            by1[k] = (float)((ci + rh) * 32);
        }

        for (int step = 0; step < n; step++) {
            // per-lane best (smallest k first => smallest index among lane's ties)
            uint32_t bkey = 0u;
            int      bidx = 0x7FFFFFFF;
#pragma unroll
            for (int k = 0; k < 4; k++) {
                if (alive[k]) {
                    uint32_t key = f2key(sc[k]);
                    if (key > bkey) { bkey = key; bidx = k * 32 + lane; }
                }
            }
            uint32_t wmax = __reduce_max_sync(0xFFFFFFFFu, bkey);
            int cand = (bkey == wmax) ? bidx : 0x7FFFFFFF;
            int bi   = __reduce_min_sync(0xFFFFFFFFu, cand);
            float bsc = key2f(wmax);

            if (lane == 0) {
                out[b * 7 + outoff[wid] + step]         = (float)(st + bi);
                out[7 * B + b * 7 + outoff[wid] + step] = bsc;
            }

            // best box from index (pure ALU, no shuffles)
            int   Bi = bi / W, Bj = bi % W;
            float BX0 = (float)(Bj * 32);
            float BY0 = (float)(Bi * 32);
            float BX1 = (float)((Bj + rw) * 32);
            float BY1 = (float)((Bi + rh) * 32);

#pragma unroll
            for (int k = 0; k < 4; k++) {
                float ix0 = fmaxf(BX0, bx0[k]);
                float iy0 = fmaxf(BY0, by0[k]);
                float ix1 = fminf(BX1, bx1[k]);
                float iy1 = fminf(BY1, by1[k]);
                float inter = fmaxf(ix1 - ix0, 0.f) * fmaxf(iy1 - iy0, 0.f);
                float iou = inter / (A + A - inter);
                if (!(iou < 0.25f)) alive[k] = false;
            }
        }
    } else {
        // ---- warps 3..11: all 361 window scores to gmem -------------------
        float* all_scores_out = out + 14 * B;
        for (int w = tid - 96; w < NWIN; w += 288) {
            int i, j, rh, rw;
            if (w < 121)      { rh = 4; rw = 4; int l = w;       i = l / 11; j = l % 11; }
            else if (w < 241) { rh = 3; rw = 5; int l = w - 121; i = l / 10; j = l % 10; }
            else              { rh = 5; rw = 3; int l = w - 241; i = l / 12; j = l % 12; }
            float s = 0.f;
            for (int di = 0; di < rh; di++)
                for (int dj = 0; dj < rw; dj++)
                    s += ssum[(i + di) * FM + (j + dj)];
            all_scores_out[b * NWIN + w] = s / (float)(rh * rw);
        }
    }
}

extern "C" void kernel_launch(void* const* d_in, const int* in_sizes, int n_in,
                              void* d_out, int out_size) {
    const float* x   = (const float*)d_in[0];
    float*       out = (float*)d_out;

    const int B = in_sizes[0] / (CH * HW);   // 64

    dim3 grid1(B, CHUNKS);
    chan_sum_kernel<<<grid1, 196>>>(x, B);

    cudaLaunchConfig_t cfg = {};
    cfg.gridDim  = dim3(B, 1, 1);
    cfg.blockDim = dim3(384, 1, 1);
    cfg.dynamicSmemBytes = 0;
    cfg.stream = 0;
    cudaLaunchAttribute attrs[1];
    attrs[0].id = cudaLaunchAttributeProgrammaticStreamSerialization;
    attrs[0].val.programmaticStreamSerializationAllowed = 1;
    cfg.attrs = attrs;
    cfg.numAttrs = 1;

    cudaError_t err = cudaLaunchKernelEx(&cfg, appm_finalize_kernel, out, B);
    if (err != cudaSuccess) {
        (void)cudaGetLastError();   // clear
        appm_finalize_kernel<<<B, 384>>>(out, B);
    }
}

// round 16
// speedup vs baseline: 1.2095x; 1.1875x over previous
#include <cuda_runtime.h>
#include <cstdint>

#define FM      14
#define HW      196          // 14*14
#define CH      2048
#define CHUNKS  16
#define CPC     (CH / CHUNKS)   // 128 channels per chunk
#define NWIN    361
#define MAXB    64

// Per-batch channel sums, accumulated via RED.ADD.F32 by the 16 chunk blocks.
// Zero at load; reset to zero by the finalize kernel each run.
__device__ float g_sum[MAXB * HW];
// Per-batch arrival counters. Zero at load; reset by finalize each run.
__device__ int g_count[MAXB];

__device__ __forceinline__ int atom_add_release_gpu(int* p, int v) {
    int old;
    asm volatile("atom.add.release.gpu.global.s32 %0, [%1], %2;"
                 : "=r"(old) : "l"(p), "r"(v) : "memory");
    return old;
}
__device__ __forceinline__ int ld_acquire_gpu(const int* p) {
    int v;
    asm volatile("ld.acquire.gpu.global.s32 %0, [%1];" : "=r"(v) : "l"(p) : "memory");
    return v;
}
__device__ __forceinline__ void red_add_f32(float* p, float v) {
    asm volatile("red.global.add.f32 [%0], %1;" :: "l"(p), "f"(v) : "memory");
}

// Monotonic float<->uint bijection (total order preserved).
__device__ __forceinline__ uint32_t f2key(float f) {
    uint32_t u = __float_as_uint(f);
    return (u & 0x80000000u) ? ~u : (u | 0x80000000u);
}
__device__ __forceinline__ float key2f(uint32_t k) {
    uint32_t u = (k & 0x80000000u) ? (k ^ 0x80000000u) : ~k;
    return __uint_as_float(u);
}

// ---------------------------------------------------------------------------
// Kernel 1: lean streaming reduction (exact R12 form): LDG.128 unroll 8,
// PDL trigger, RED.ADD accumulation into g_sum, release-atomic arrival.
// ---------------------------------------------------------------------------
__global__ __launch_bounds__(196) void chan_sum_kernel(const float* __restrict__ x, int B) {
    asm volatile("griddepcontrol.launch_dependents;" ::: "memory");

    const int b     = blockIdx.x;
    const int chunk = blockIdx.y;
    const int tid   = threadIdx.x;          // 0..195
    const int grp   = tid / 49;             // 0..3
    const int v     = tid - grp * 49;       // 0..48

    const float4* base = reinterpret_cast<const float4*>(
        x + ((size_t)b * CH + (size_t)chunk * CPC) * HW);

    float4 acc = make_float4(0.f, 0.f, 0.f, 0.f);
#pragma unroll 8
    for (int c = grp; c < CPC; c += 4) {
        float4 t = base[c * 49 + v];
        acc.x += t.x; acc.y += t.y; acc.z += t.z; acc.w += t.w;
    }

    __shared__ float4 red[4 * 49];
    red[grp * 49 + v] = acc;
    __syncthreads();

    if (tid < HW) {
        const float* rf = reinterpret_cast<const float*>(red);
        red_add_f32(&g_sum[b * HW + tid],
                    rf[tid] + rf[HW + tid] + rf[2 * HW + tid] + rf[3 * HW + tid]);
    }
    __syncthreads();
    if (tid == 0) (void)atom_add_release_gpu(&g_count[b], 1);
}

// ---------------------------------------------------------------------------
// NMS for one ratio group, all parameters compile-time. Scores come from the
// precomputed smem array (parallel phase); boxes derived arithmetically.
// ---------------------------------------------------------------------------
template<int RH, int RW, int W, int CNT, int N, int OUTOFF, int ST>
__device__ __forceinline__ void nms_group(const float* __restrict__ scores,
                                          float* __restrict__ out,
                                          int b, int B, int lane)
{
    constexpr float A = (float)(RH * 32 * RW * 32);   // constant box area

    float sc[4];
    float bx0[4], by0[4], bx1[4], by1[4];
    bool  alive[4];
#pragma unroll
    for (int k = 0; k < 4; k++) {
        const int ii = k * 32 + lane;
        const bool valid = (ii < CNT);
        alive[k] = valid;
        const int ci = (valid ? ii : 0) / W;
        const int cj = (valid ? ii : 0) % W;
        sc[k]  = valid ? scores[ST + ii] : 0.f;
        bx0[k] = (float)(cj * 32);
        by0[k] = (float)(ci * 32);
        bx1[k] = (float)((cj + RW) * 32);
        by1[k] = (float)((ci + RH) * 32);
    }

#pragma unroll
    for (int step = 0; step < N; step++) {
        // per-lane best; smallest k first => smallest index among lane ties
        uint32_t bkey = 0u;
        int      bidx = 0x7FFFFFFF;
#pragma unroll
        for (int k = 0; k < 4; k++) {
            if (alive[k]) {
                uint32_t key = f2key(sc[k]);
                if (key > bkey) { bkey = key; bidx = k * 32 + lane; }
            }
        }
        uint32_t wmax = __reduce_max_sync(0xFFFFFFFFu, bkey);
        int cand = (bkey == wmax) ? bidx : 0x7FFFFFFF;
        int bi   = __reduce_min_sync(0xFFFFFFFFu, cand);
        float bsc = key2f(wmax);

        if (lane == 0) {
            out[b * 7 + OUTOFF + step]         = (float)(ST + bi);
            out[7 * B + b * 7 + OUTOFF + step] = bsc;
        }

        // best box from index (pure ALU, compile-time W)
        const int   Bi = bi / W, Bj = bi % W;
        const float BX0 = (float)(Bj * 32);
        const float BY0 = (float)(Bi * 32);
        const float BX1 = (float)((Bj + RW) * 32);
        const float BY1 = (float)((Bi + RH) * 32);

#pragma unroll
        for (int k = 0; k < 4; k++) {
            float ix0 = fmaxf(BX0, bx0[k]);
            float iy0 = fmaxf(BY0, by0[k]);
            float ix1 = fminf(BX1, bx1[k]);
            float iy1 = fminf(BY1, by1[k]);
            float inter = fmaxf(ix1 - ix0, 0.f) * fmaxf(iy1 - iy0, 0.f);
            float iou = inter / (A + A - inter);
            if (!(iou < 0.25f)) alive[k] = false;
        }
    }
}

// ---------------------------------------------------------------------------
// Kernel 2: finalize (PDL co-scheduled). Proven R12 phase structure:
//  single tid==0 nanosleep poll -> ssum -> scores to smem + all_scores
//  stores by ALL 384 threads in parallel -> sync -> templated redux NMS.
// Output layout (fp32): [B*7 indices][B*7 window scores][B*361 all_scores]
// ---------------------------------------------------------------------------
__global__ __launch_bounds__(384) void appm_finalize_kernel(float* __restrict__ out, int B)
{
    const int b    = blockIdx.x;
    const int tid  = threadIdx.x;
    const int wid  = tid >> 5;
    const int lane = tid & 31;

    __shared__ float ssum[HW];
    __shared__ float scores[NWIN];

    // Wait for this batch's 16 chunk partials (single low-pressure poller).
    if (tid == 0) {
        while (ld_acquire_gpu(&g_count[b]) < CHUNKS) __nanosleep(32);
        g_count[b] = 0;   // reset for next graph replay
    }
    __syncthreads();

    if (tid < HW) {
        ssum[tid] = __ldcg(&g_sum[b * HW + tid]);
        g_sum[b * HW + tid] = 0.f;   // reset for next graph replay
    }
    __syncthreads();

    // Parallel window-score phase: ~1 window per thread (384 >= 361).
    float* all_scores_out = out + 14 * B;
    for (int w = tid; w < NWIN; w += 384) {
        int i, j, rh, rw;
        if (w < 121)      { rh = 4; rw = 4; int l = w;       i = l / 11; j = l % 11; }
        else if (w < 241) { rh = 3; rw = 5; int l = w - 121; i = l / 10; j = l % 10; }
        else              { rh = 5; rw = 3; int l = w - 241; i = l / 12; j = l % 12; }
        float s = 0.f;
        for (int di = 0; di < rh; di++)
            for (int dj = 0; dj < rw; dj++)
                s += ssum[(i + di) * FM + (j + dj)];
        s /= (float)(rh * rw);
        scores[w] = s;
        all_scores_out[b * NWIN + w] = s;
    }
    __syncthreads();

    if (wid == 0)      nms_group<4, 4, 11, 121, 2, 0, 0>  (scores, out, b, B, lane);
    else if (wid == 1) nms_group<3, 5, 10, 120, 3, 2, 121>(scores, out, b, B, lane);
    else if (wid == 2) nms_group<5, 3, 12, 120, 2, 5, 241>(scores, out, b, B, lane);
}

extern "C" void kernel_launch(void* const* d_in, const int* in_sizes, int n_in,
                              void* d_out, int out_size) {
    const float* x   = (const float*)d_in[0];
    float*       out = (float*)d_out;

    const int B = in_sizes[0] / (CH * HW);   // 64

    dim3 grid1(B, CHUNKS);
    chan_sum_kernel<<<grid1, 196>>>(x, B);

    cudaLaunchConfig_t cfg = {};
    cfg.gridDim  = dim3(B, 1, 1);
    cfg.blockDim = dim3(384, 1, 1);
    cfg.dynamicSmemBytes = 0;
    cfg.stream = 0;
    cudaLaunchAttribute attrs[1];
    attrs[0].id = cudaLaunchAttributeProgrammaticStreamSerialization;
    attrs[0].val.programmaticStreamSerializationAllowed = 1;
    cfg.attrs = attrs;
    cfg.numAttrs = 1;

    cudaError_t err = cudaLaunchKernelEx(&cfg, appm_finalize_kernel, out, B);
    if (err != cudaSuccess) {
        (void)cudaGetLastError();   // clear
        appm_finalize_kernel<<<B, 384>>>(out, B);
    }
}